// round 9
// baseline (speedup 1.0000x reference)
#include <cuda_runtime.h>
#include <math.h>

#define NE 2048
#define NX 3
#define NB 512      // persistent grid: 512 blocks (all co-resident at 4/SM x 148)
#define NT 128      // threads per block

// Scratch (allocation-free): all __device__ globals.
__device__ float g_s[NX][NE];        // static RHS (SC + last-column terms)
__device__ float g_s2[NX][NE];       // extended RHS for lower rows
__device__ float g_Binv[NX*NX][NE];  // per-bin 3x3 inverse of B_i
__device__ float g_c[NE];            // c_j = dy*E_j
__device__ float g_F[2][NX][NE];     // double-buffered solution
__device__ float g_wF[2][NX][NE];    // double-buffered c_j*F_j (col NE-1 == 0)
__device__ unsigned g_count;         // barrier arrival counter (self-resetting)
__device__ unsigned g_gen;           // barrier generation (monotonic)

__device__ __forceinline__ float4 ld4(const float* __restrict__ p, int j) {
    return *reinterpret_cast<const float4*>(p + j);
}

// ---------------------------------------------------------------------------
// Grid-wide barrier. Safe because all NB blocks are co-resident
// (__launch_bounds__(NT,4): 148 SMs x 4 blocks = 592 >= 512).
// g_count self-resets each barrier; g_gen grows monotonically across replays.
// ---------------------------------------------------------------------------
__device__ __forceinline__ void grid_barrier() {
    __syncthreads();
    if (threadIdx.x == 0) {
        __threadfence();
        volatile unsigned* vgen = (volatile unsigned*)&g_gen;
        unsigned gen = *vgen;
        if (atomicAdd(&g_count, 1u) == NB - 1u) {
            atomicExch(&g_count, 0u);
            __threadfence();
            atomicExch(&g_gen, gen + 1u);
        } else {
            while (*vgen == gen) __nanosleep(32);
            __threadfence();
        }
    }
    __syncthreads();
}

#define DECLARE_K_STREAMS(K, i)                                                \
    const float* __restrict__ k00 = K + ((size_t)((0*NX+0)*NE + i))*NE;        \
    const float* __restrict__ k01 = K + ((size_t)((0*NX+1)*NE + i))*NE;        \
    const float* __restrict__ k02 = K + ((size_t)((0*NX+2)*NE + i))*NE;        \
    const float* __restrict__ k10 = K + ((size_t)((1*NX+0)*NE + i))*NE;        \
    const float* __restrict__ k11 = K + ((size_t)((1*NX+1)*NE + i))*NE;        \
    const float* __restrict__ k12 = K + ((size_t)((1*NX+2)*NE + i))*NE;        \
    const float* __restrict__ k20 = K + ((size_t)((2*NX+0)*NE + i))*NE;        \
    const float* __restrict__ k21 = K + ((size_t)((2*NX+1)*NE + i))*NE;        \
    const float* __restrict__ k22 = K + ((size_t)((2*NX+2)*NE + i))*NE;

#define ACCUM(JB, W0, W1, W2)                                                  \
    do {                                                                       \
        float4 kk;                                                             \
        kk = ld4(k00, JB); y0 += kk.x*W0.x + kk.y*W0.y + kk.z*W0.z + kk.w*W0.w;\
        kk = ld4(k01, JB); y0 += kk.x*W1.x + kk.y*W1.y + kk.z*W1.z + kk.w*W1.w;\
        kk = ld4(k02, JB); y0 += kk.x*W2.x + kk.y*W2.y + kk.z*W2.z + kk.w*W2.w;\
        kk = ld4(k10, JB); y1 += kk.x*W0.x + kk.y*W0.y + kk.z*W0.z + kk.w*W0.w;\
        kk = ld4(k11, JB); y1 += kk.x*W1.x + kk.y*W1.y + kk.z*W1.z + kk.w*W1.w;\
        kk = ld4(k12, JB); y1 += kk.x*W2.x + kk.y*W2.y + kk.z*W2.z + kk.w*W2.w;\
        kk = ld4(k20, JB); y2 += kk.x*W0.x + kk.y*W0.y + kk.z*W0.z + kk.w*W0.w;\
        kk = ld4(k21, JB); y2 += kk.x*W1.x + kk.y*W1.y + kk.z*W1.z + kk.w*W1.w;\
        kk = ld4(k22, JB); y2 += kk.x*W2.x + kk.y*W2.y + kk.z*W2.z + kk.w*W2.w;\
    } while (0)

// ---------------------------------------------------------------------------
// Setup math for one bin i (writes s, Binv, c, F0/wF0 into buffer 0)
// ---------------------------------------------------------------------------
__device__ void setup_bin(
    int i, const float* __restrict__ E, const float* __restrict__ R,
    const float* __restrict__ K, const float* __restrict__ S0,
    const float* __restrict__ SC)
{
    const float dy = logf(E[NE-1] / E[0]) / (float)(NE - 1);

    float srcl[NX];
#pragma unroll
    for (int p = 0; p < NX; p++) srcl[p] = S0[p] / R[p*NE + NE-1];

    float Flast[NX];
#pragma unroll
    for (int x = 0; x < NX; x++) {
        float acc = SC[x*NE + NE-1];
#pragma unroll
        for (int p = 0; p < NX; p++)
            acc += K[((size_t)((x*NX + p)*NE + (NE-1)))*NE + (NE-1)] * srcl[p];
        Flast[x] = acc / R[x*NE + NE-1];
    }

    if (i == NE-1) {
#pragma unroll
        for (int x = 0; x < NX; x++) {
            g_F[0][x][NE-1] = Flast[x];
            g_F[1][x][NE-1] = Flast[x];
            g_wF[0][x][NE-1] = 0.0f;   // sentinel: j=NE-1 handled inside s
            g_wF[1][x][NE-1] = 0.0f;
        }
        return;
    }

    const float ci = dy * E[i];
    g_c[i] = ci;
    const float w_last = 0.5f * dy * E[NE-1];

    float Bm[3][3];
    float sv[NX];
#pragma unroll
    for (int x = 0; x < NX; x++) {
        float acc = SC[x*NE + i];
#pragma unroll
        for (int p = 0; p < NX; p++) {
            size_t rb = ((size_t)((x*NX + p)*NE + i)) * NE;
            float Kii = K[rb + i];
            float Kil = K[rb + NE-1];
            Bm[x][p] = -0.5f * ci * Kii + ((x == p) ? R[x*NE + i] : 0.0f);
            acc += Kil * (w_last * Flast[p] + srcl[p]);
        }
        sv[x] = acc;
    }

    float c00 = Bm[1][1]*Bm[2][2] - Bm[1][2]*Bm[2][1];
    float c01 = Bm[1][2]*Bm[2][0] - Bm[1][0]*Bm[2][2];
    float c02 = Bm[1][0]*Bm[2][1] - Bm[1][1]*Bm[2][0];
    float det = Bm[0][0]*c00 + Bm[0][1]*c01 + Bm[0][2]*c02;
    float id  = 1.0f / det;
    float inv[3][3];
    inv[0][0] = c00 * id;
    inv[0][1] = (Bm[0][2]*Bm[2][1] - Bm[0][1]*Bm[2][2]) * id;
    inv[0][2] = (Bm[0][1]*Bm[1][2] - Bm[0][2]*Bm[1][1]) * id;
    inv[1][0] = c01 * id;
    inv[1][1] = (Bm[0][0]*Bm[2][2] - Bm[0][2]*Bm[2][0]) * id;
    inv[1][2] = (Bm[0][2]*Bm[1][0] - Bm[0][0]*Bm[1][2]) * id;
    inv[2][0] = c02 * id;
    inv[2][1] = (Bm[0][1]*Bm[2][0] - Bm[0][0]*Bm[2][1]) * id;
    inv[2][2] = (Bm[0][0]*Bm[1][1] - Bm[0][1]*Bm[1][0]) * id;

#pragma unroll
    for (int x = 0; x < NX; x++) {
        g_s[x][i] = sv[x];
#pragma unroll
        for (int p = 0; p < NX; p++) g_Binv[x*NX + p][i] = inv[x][p];
    }

#pragma unroll
    for (int x = 0; x < NX; x++) {
        float f = inv[x][0]*sv[0] + inv[x][1]*sv[1] + inv[x][2]*sv[2];
        g_F[0][x][i]  = f;
        g_wF[0][x][i] = ci * f;
    }
}

// ---------------------------------------------------------------------------
// One Jacobi row update (128 threads):
//   y = sum_{p, j in (i, col_hi)} K[x][p][i][j] * wF[src][p][j]
//   F[dst][:,i] = Binv_i * (s_in[:,i] + y)
// ---------------------------------------------------------------------------
__device__ void sweep_row(
    int i, const float* __restrict__ K, int src, int dst, int col_hi,
    int use_s2, float red[3][4], int tid, int lane, int warp)
{
    const float* __restrict__ wf0 = g_wF[src][0];
    const float* __restrict__ wf1 = g_wF[src][1];
    const float* __restrict__ wf2 = g_wF[src][2];
    DECLARE_K_STREAMS(K, i)

    float y0 = 0.f, y1 = 0.f, y2 = 0.f;
    int jv = (i + 1) & ~3;           // 16B-aligned start
    int jb = jv + 4 * tid;

    if (jb < col_hi) {
        // first pass: mask elements with j <= i (only lowest chunk can hit)
        float4 w0 = ld4(wf0, jb), w1 = ld4(wf1, jb), w2 = ld4(wf2, jb);
        if (jb + 0 <= i) { w0.x = 0.f; w1.x = 0.f; w2.x = 0.f; }
        if (jb + 1 <= i) { w0.y = 0.f; w1.y = 0.f; w2.y = 0.f; }
        if (jb + 2 <= i) { w0.z = 0.f; w1.z = 0.f; w2.z = 0.f; }
        if (jb + 3 <= i) { w0.w = 0.f; w1.w = 0.f; w2.w = 0.f; }
        ACCUM(jb, w0, w1, w2);
        jb += 4 * NT;
    }
#pragma unroll 2
    for (; jb < col_hi; jb += 4 * NT) {
        float4 w0 = ld4(wf0, jb), w1 = ld4(wf1, jb), w2 = ld4(wf2, jb);
        ACCUM(jb, w0, w1, w2);
    }

#pragma unroll
    for (int o = 16; o > 0; o >>= 1) {
        y0 += __shfl_xor_sync(0xffffffffu, y0, o);
        y1 += __shfl_xor_sync(0xffffffffu, y1, o);
        y2 += __shfl_xor_sync(0xffffffffu, y2, o);
    }
    if (lane == 0) { red[0][warp] = y0; red[1][warp] = y1; red[2][warp] = y2; }
    __syncthreads();

    if (tid == 0) {
        float s0, s1, s2;
        if (use_s2) { s0 = g_s2[0][i]; s1 = g_s2[1][i]; s2 = g_s2[2][i]; }
        else        { s0 = g_s [0][i]; s1 = g_s [1][i]; s2 = g_s [2][i]; }
#pragma unroll
        for (int w = 0; w < 4; w++) {
            s0 += red[0][w]; s1 += red[1][w]; s2 += red[2][w];
        }
        float f0 = g_Binv[0][i]*s0 + g_Binv[1][i]*s1 + g_Binv[2][i]*s2;
        float f1 = g_Binv[3][i]*s0 + g_Binv[4][i]*s1 + g_Binv[5][i]*s2;
        float f2 = g_Binv[6][i]*s0 + g_Binv[7][i]*s1 + g_Binv[8][i]*s2;
        float ci = g_c[i];
        g_F[dst][0][i]  = f0;  g_wF[dst][0][i] = ci * f0;
        g_F[dst][1][i]  = f1;  g_wF[dst][1][i] = ci * f1;
        g_F[dst][2][i]  = f2;  g_wF[dst][2][i] = ci * f2;
    }
    __syncthreads();             // smem reuse guard for next row in this block
}

// ---------------------------------------------------------------------------
// Accumulate solved upper half into one lower row's RHS:
// g_s2[:,i] = g_s[:,i] + sum_{p, j in [1024,2048)} K[x][p][i][j]*wF[src][p][j]
// 128 threads x 4 cols x 2 passes = 1024 columns.
// ---------------------------------------------------------------------------
__device__ void accum_row(
    int i, const float* __restrict__ K, int src,
    float red[3][4], int tid, int lane, int warp)
{
    const float* __restrict__ wf0 = g_wF[src][0];
    const float* __restrict__ wf1 = g_wF[src][1];
    const float* __restrict__ wf2 = g_wF[src][2];
    DECLARE_K_STREAMS(K, i)

    float y0 = 0.f, y1 = 0.f, y2 = 0.f;
#pragma unroll
    for (int pass = 0; pass < 2; pass++) {
        int jb = NE/2 + pass * (4 * NT) + 4 * tid;
        float4 w0 = ld4(wf0, jb), w1 = ld4(wf1, jb), w2 = ld4(wf2, jb);
        ACCUM(jb, w0, w1, w2);
    }

#pragma unroll
    for (int o = 16; o > 0; o >>= 1) {
        y0 += __shfl_xor_sync(0xffffffffu, y0, o);
        y1 += __shfl_xor_sync(0xffffffffu, y1, o);
        y2 += __shfl_xor_sync(0xffffffffu, y2, o);
    }
    if (lane == 0) { red[0][warp] = y0; red[1][warp] = y1; red[2][warp] = y2; }
    __syncthreads();

    if (tid == 0) {
        float s0 = g_s[0][i], s1 = g_s[1][i], s2 = g_s[2][i];
#pragma unroll
        for (int w = 0; w < 4; w++) {
            s0 += red[0][w]; s1 += red[1][w]; s2 += red[2][w];
        }
        g_s2[0][i] = s0; g_s2[1][i] = s1; g_s2[2][i] = s2;
    }
    __syncthreads();
}

// ---------------------------------------------------------------------------
// Persistent solver: setup -> 3 upper sweeps -> accum -> 2 lower sweeps -> out
// Buffers: upper final in 1 (0->1->0->1); lower F0 in 0, final in 0 (0->1->0).
// ---------------------------------------------------------------------------
__global__ void __launch_bounds__(NT, 4) solve_kernel(
    const float* __restrict__ E, const float* __restrict__ R,
    const float* __restrict__ K, const float* __restrict__ S0,
    const float* __restrict__ SC, float* __restrict__ out)
{
    __shared__ float red[3][4];
    int tid  = threadIdx.x;
    int lane = tid & 31;
    int warp = tid >> 5;
    int b    = blockIdx.x;

    // Phase 0: setup (blocks 0..15 cover all 2048 bins)
    if (b < NE / NT) setup_bin(b * NT + tid, E, R, K, S0, SC);
    grid_barrier();

    // Phases 1-3: upper-half Jacobi (rows 1024..2046, j in (i,2048))
    {
        int r0 = NE/2 + b;           // 1024..1535
        int r1 = NE - 2 - b;         // 2046..1535
        sweep_row(r0, K, 0, 1, NE, 0, red, tid, lane, warp);
        if (r1 != r0) sweep_row(r1, K, 0, 1, NE, 0, red, tid, lane, warp);
        grid_barrier();
        sweep_row(r0, K, 1, 0, NE, 0, red, tid, lane, warp);
        if (r1 != r0) sweep_row(r1, K, 1, 0, NE, 0, red, tid, lane, warp);
        grid_barrier();
        sweep_row(r0, K, 0, 1, NE, 0, red, tid, lane, warp);
        if (r1 != r0) sweep_row(r1, K, 0, 1, NE, 0, red, tid, lane, warp);
        grid_barrier();
    }

    // Phase 4: fold upper half (buffer 1) into lower rows' RHS
    accum_row(b,      K, 1, red, tid, lane, warp);
    accum_row(b + NB, K, 1, red, tid, lane, warp);
    grid_barrier();

    // Phases 5-6: lower-half Jacobi (rows 0..1023, j in (i,1024), RHS = s2)
    {
        int r0 = b;                  // 0..511
        int r1 = NE/2 - 1 - b;       // 1023..512
        sweep_row(r0, K, 0, 1, NE/2, 1, red, tid, lane, warp);
        sweep_row(r1, K, 0, 1, NE/2, 1, red, tid, lane, warp);
        grid_barrier();
        sweep_row(r0, K, 1, 0, NE/2, 1, red, tid, lane, warp);
        sweep_row(r1, K, 1, 0, NE/2, 1, red, tid, lane, warp);
        grid_barrier();
    }

    // Phase 7: write output (lower half from buf 0, upper half from buf 1)
    if (b < NE / NT) {
        int i = b * NT + tid;
        out[i] = E[i];
        int buf = (i < NE/2) ? 0 : 1;
#pragma unroll
        for (int x = 0; x < NX; x++) {
            float f = g_F[buf][x][i];
            out[(x + 1) * NE + i] = (f > 0.0f) ? f : 0.0f;
        }
    }
}

extern "C" void kernel_launch(void* const* d_in, const int* in_sizes, int n_in,
                              void* d_out, int out_size)
{
    const float* E  = (const float*)d_in[0];
    const float* R  = (const float*)d_in[1];
    const float* K  = (const float*)d_in[2];
    const float* S0 = (const float*)d_in[3];
    const float* SC = (const float*)d_in[4];
    float* out = (float*)d_out;

    solve_kernel<<<NB, NT>>>(E, R, K, S0, SC, out);
}

// round 11
// speedup vs baseline: 1.0212x; 1.0212x over previous
#include <cuda_runtime.h>
#include <math.h>

#define NE 2048
#define NX 3
#define NB 1024     // persistent grid; co-resident: 148 SMs x 8 blocks = 1184 >= 1024
#define NT 128

// Scratch (allocation-free): all __device__ globals.
__device__ float g_s[NX][NE];        // static RHS (SC + last-column terms)
__device__ float g_s2[NX][NE];       // extended RHS for lower rows
__device__ float g_Binv[NX*NX][NE];  // per-bin 3x3 inverse of B_i
__device__ float g_c[NE];            // c_j = dy*E_j
__device__ float g_F[2][NX][NE];     // double-buffered solution
__device__ float g_wF[2][NX][NE];    // double-buffered c_j*F_j (col NE-1 == 0)
__device__ unsigned g_count;         // barrier arrival counter (self-resetting)
__device__ unsigned g_gen;           // barrier generation (monotonic)

__device__ __forceinline__ float4 ld4(const float* __restrict__ p, int j) {
    return *reinterpret_cast<const float4*>(p + j);
}

// ---------------------------------------------------------------------------
// Grid-wide barrier; all NB blocks are co-resident by __launch_bounds__(NT,8).
// Waiters back off with __nanosleep to keep L2 traffic off the hot line.
// ---------------------------------------------------------------------------
__device__ __forceinline__ void grid_barrier() {
    __syncthreads();
    if (threadIdx.x == 0) {
        __threadfence();
        volatile unsigned* vgen = (volatile unsigned*)&g_gen;
        unsigned gen = *vgen;
        if (atomicAdd(&g_count, 1u) == NB - 1u) {
            atomicExch(&g_count, 0u);
            __threadfence();
            atomicExch(&g_gen, gen + 1u);
        } else {
            while (*vgen == gen) __nanosleep(32);
            __threadfence();
        }
    }
    __syncthreads();
}

#define DECLARE_K_STREAMS(K, i)                                                \
    const float* __restrict__ k00 = K + ((size_t)((0*NX+0)*NE + i))*NE;        \
    const float* __restrict__ k01 = K + ((size_t)((0*NX+1)*NE + i))*NE;        \
    const float* __restrict__ k02 = K + ((size_t)((0*NX+2)*NE + i))*NE;        \
    const float* __restrict__ k10 = K + ((size_t)((1*NX+0)*NE + i))*NE;        \
    const float* __restrict__ k11 = K + ((size_t)((1*NX+1)*NE + i))*NE;        \
    const float* __restrict__ k12 = K + ((size_t)((1*NX+2)*NE + i))*NE;        \
    const float* __restrict__ k20 = K + ((size_t)((2*NX+0)*NE + i))*NE;        \
    const float* __restrict__ k21 = K + ((size_t)((2*NX+1)*NE + i))*NE;        \
    const float* __restrict__ k22 = K + ((size_t)((2*NX+2)*NE + i))*NE;

#define ACCUM(JB, W0, W1, W2)                                                  \
    do {                                                                       \
        float4 kk;                                                             \
        kk = ld4(k00, JB); y0 += kk.x*W0.x + kk.y*W0.y + kk.z*W0.z + kk.w*W0.w;\
        kk = ld4(k01, JB); y0 += kk.x*W1.x + kk.y*W1.y + kk.z*W1.z + kk.w*W1.w;\
        kk = ld4(k02, JB); y0 += kk.x*W2.x + kk.y*W2.y + kk.z*W2.z + kk.w*W2.w;\
        kk = ld4(k10, JB); y1 += kk.x*W0.x + kk.y*W0.y + kk.z*W0.z + kk.w*W0.w;\
        kk = ld4(k11, JB); y1 += kk.x*W1.x + kk.y*W1.y + kk.z*W1.z + kk.w*W1.w;\
        kk = ld4(k12, JB); y1 += kk.x*W2.x + kk.y*W2.y + kk.z*W2.z + kk.w*W2.w;\
        kk = ld4(k20, JB); y2 += kk.x*W0.x + kk.y*W0.y + kk.z*W0.z + kk.w*W0.w;\
        kk = ld4(k21, JB); y2 += kk.x*W1.x + kk.y*W1.y + kk.z*W1.z + kk.w*W1.w;\
        kk = ld4(k22, JB); y2 += kk.x*W2.x + kk.y*W2.y + kk.z*W2.z + kk.w*W2.w;\
    } while (0)

// ---------------------------------------------------------------------------
// Setup math for one bin i (writes s, Binv, c, F0/wF0 into buffer 0)
// ---------------------------------------------------------------------------
__device__ void setup_bin(
    int i, const float* __restrict__ E, const float* __restrict__ R,
    const float* __restrict__ K, const float* __restrict__ S0,
    const float* __restrict__ SC)
{
    const float dy = logf(E[NE-1] / E[0]) / (float)(NE - 1);

    float srcl[NX];
#pragma unroll
    for (int p = 0; p < NX; p++) srcl[p] = S0[p] / R[p*NE + NE-1];

    float Flast[NX];
#pragma unroll
    for (int x = 0; x < NX; x++) {
        float acc = SC[x*NE + NE-1];
#pragma unroll
        for (int p = 0; p < NX; p++)
            acc += K[((size_t)((x*NX + p)*NE + (NE-1)))*NE + (NE-1)] * srcl[p];
        Flast[x] = acc / R[x*NE + NE-1];
    }

    if (i == NE-1) {
#pragma unroll
        for (int x = 0; x < NX; x++) {
            g_F[0][x][NE-1] = Flast[x];
            g_F[1][x][NE-1] = Flast[x];
            g_wF[0][x][NE-1] = 0.0f;   // sentinel: j=NE-1 handled inside s
            g_wF[1][x][NE-1] = 0.0f;
        }
        return;
    }

    const float ci = dy * E[i];
    g_c[i] = ci;
    const float w_last = 0.5f * dy * E[NE-1];

    float Bm[3][3];
    float sv[NX];
#pragma unroll
    for (int x = 0; x < NX; x++) {
        float acc = SC[x*NE + i];
#pragma unroll
        for (int p = 0; p < NX; p++) {
            size_t rb = ((size_t)((x*NX + p)*NE + i)) * NE;
            float Kii = K[rb + i];
            float Kil = K[rb + NE-1];
            Bm[x][p] = -0.5f * ci * Kii + ((x == p) ? R[x*NE + i] : 0.0f);
            acc += Kil * (w_last * Flast[p] + srcl[p]);
        }
        sv[x] = acc;
    }

    float c00 = Bm[1][1]*Bm[2][2] - Bm[1][2]*Bm[2][1];
    float c01 = Bm[1][2]*Bm[2][0] - Bm[1][0]*Bm[2][2];
    float c02 = Bm[1][0]*Bm[2][1] - Bm[1][1]*Bm[2][0];
    float det = Bm[0][0]*c00 + Bm[0][1]*c01 + Bm[0][2]*c02;
    float id  = 1.0f / det;
    float inv[3][3];
    inv[0][0] = c00 * id;
    inv[0][1] = (Bm[0][2]*Bm[2][1] - Bm[0][1]*Bm[2][2]) * id;
    inv[0][2] = (Bm[0][1]*Bm[1][2] - Bm[0][2]*Bm[1][1]) * id;
    inv[1][0] = c01 * id;
    inv[1][1] = (Bm[0][0]*Bm[2][2] - Bm[0][2]*Bm[2][0]) * id;
    inv[1][2] = (Bm[0][2]*Bm[1][0] - Bm[0][0]*Bm[1][2]) * id;
    inv[2][0] = c02 * id;
    inv[2][1] = (Bm[0][1]*Bm[2][0] - Bm[0][0]*Bm[2][1]) * id;
    inv[2][2] = (Bm[0][0]*Bm[1][1] - Bm[0][1]*Bm[1][0]) * id;

#pragma unroll
    for (int x = 0; x < NX; x++) {
        g_s[x][i] = sv[x];
#pragma unroll
        for (int p = 0; p < NX; p++) g_Binv[x*NX + p][i] = inv[x][p];
    }

#pragma unroll
    for (int x = 0; x < NX; x++) {
        float f = inv[x][0]*sv[0] + inv[x][1]*sv[1] + inv[x][2]*sv[2];
        g_F[0][x][i]  = f;
        g_wF[0][x][i] = ci * f;
    }
}

// ---------------------------------------------------------------------------
// One Jacobi row update (128 threads, one row per block):
//   y = sum_{p, j in (i, col_hi)} K[x][p][i][j] * wF[src][p][j]
//   F[dst][:,i] = Binv_i * (s_in[:,i] + y)
// ---------------------------------------------------------------------------
__device__ void sweep_row(
    int i, const float* __restrict__ K, int src, int dst, int col_hi,
    int use_s2, float red[3][4], int tid, int lane, int warp)
{
    const float* __restrict__ wf0 = g_wF[src][0];
    const float* __restrict__ wf1 = g_wF[src][1];
    const float* __restrict__ wf2 = g_wF[src][2];
    DECLARE_K_STREAMS(K, i)

    float y0 = 0.f, y1 = 0.f, y2 = 0.f;
    int jv = (i + 1) & ~3;           // 16B-aligned start
    int jb = jv + 4 * tid;

    if (jb < col_hi) {
        // first pass: mask elements with j <= i (only lowest chunk can hit)
        float4 w0 = ld4(wf0, jb), w1 = ld4(wf1, jb), w2 = ld4(wf2, jb);
        if (jb + 0 <= i) { w0.x = 0.f; w1.x = 0.f; w2.x = 0.f; }
        if (jb + 1 <= i) { w0.y = 0.f; w1.y = 0.f; w2.y = 0.f; }
        if (jb + 2 <= i) { w0.z = 0.f; w1.z = 0.f; w2.z = 0.f; }
        if (jb + 3 <= i) { w0.w = 0.f; w1.w = 0.f; w2.w = 0.f; }
        ACCUM(jb, w0, w1, w2);
        jb += 4 * NT;
    }
#pragma unroll 1
    for (; jb < col_hi; jb += 4 * NT) {
        float4 w0 = ld4(wf0, jb), w1 = ld4(wf1, jb), w2 = ld4(wf2, jb);
        ACCUM(jb, w0, w1, w2);
    }

#pragma unroll
    for (int o = 16; o > 0; o >>= 1) {
        y0 += __shfl_xor_sync(0xffffffffu, y0, o);
        y1 += __shfl_xor_sync(0xffffffffu, y1, o);
        y2 += __shfl_xor_sync(0xffffffffu, y2, o);
    }
    if (lane == 0) { red[0][warp] = y0; red[1][warp] = y1; red[2][warp] = y2; }
    __syncthreads();

    if (tid == 0) {
        float s0, s1, s2;
        if (use_s2) { s0 = g_s2[0][i]; s1 = g_s2[1][i]; s2 = g_s2[2][i]; }
        else        { s0 = g_s [0][i]; s1 = g_s [1][i]; s2 = g_s [2][i]; }
#pragma unroll
        for (int w = 0; w < 4; w++) {
            s0 += red[0][w]; s1 += red[1][w]; s2 += red[2][w];
        }
        float f0 = g_Binv[0][i]*s0 + g_Binv[1][i]*s1 + g_Binv[2][i]*s2;
        float f1 = g_Binv[3][i]*s0 + g_Binv[4][i]*s1 + g_Binv[5][i]*s2;
        float f2 = g_Binv[6][i]*s0 + g_Binv[7][i]*s1 + g_Binv[8][i]*s2;
        float ci = g_c[i];
        g_F[dst][0][i]  = f0;  g_wF[dst][0][i] = ci * f0;
        g_F[dst][1][i]  = f1;  g_wF[dst][1][i] = ci * f1;
        g_F[dst][2][i]  = f2;  g_wF[dst][2][i] = ci * f2;
    }
    __syncthreads();             // smem reuse guard
}

// ---------------------------------------------------------------------------
// Accumulate solved upper half into one lower row's RHS:
// g_s2[:,i] = g_s[:,i] + sum_{p, j in [1024,2048)} K[x][p][i][j]*wF[src][p][j]
// 128 threads x 4 cols x 2 passes = 1024 columns.
// ---------------------------------------------------------------------------
__device__ void accum_row(
    int i, const float* __restrict__ K, int src,
    float red[3][4], int tid, int lane, int warp)
{
    const float* __restrict__ wf0 = g_wF[src][0];
    const float* __restrict__ wf1 = g_wF[src][1];
    const float* __restrict__ wf2 = g_wF[src][2];
    DECLARE_K_STREAMS(K, i)

    float y0 = 0.f, y1 = 0.f, y2 = 0.f;
#pragma unroll 1
    for (int pass = 0; pass < 2; pass++) {
        int jb = NE/2 + pass * (4 * NT) + 4 * tid;
        float4 w0 = ld4(wf0, jb), w1 = ld4(wf1, jb), w2 = ld4(wf2, jb);
        ACCUM(jb, w0, w1, w2);
    }

#pragma unroll
    for (int o = 16; o > 0; o >>= 1) {
        y0 += __shfl_xor_sync(0xffffffffu, y0, o);
        y1 += __shfl_xor_sync(0xffffffffu, y1, o);
        y2 += __shfl_xor_sync(0xffffffffu, y2, o);
    }
    if (lane == 0) { red[0][warp] = y0; red[1][warp] = y1; red[2][warp] = y2; }
    __syncthreads();

    if (tid == 0) {
        float s0 = g_s[0][i], s1 = g_s[1][i], s2 = g_s[2][i];
#pragma unroll
        for (int w = 0; w < 4; w++) {
            s0 += red[0][w]; s1 += red[1][w]; s2 += red[2][w];
        }
        g_s2[0][i] = s0; g_s2[1][i] = s1; g_s2[2][i] = s2;
    }
    __syncthreads();
}

// ---------------------------------------------------------------------------
// Persistent solver: setup -> 3 upper sweeps -> accum -> 2 lower sweeps -> out
// Upper rows: buf 0 -> 1 -> 0 -> 1 (final in 1). Lower rows: 0 -> 1 -> 0.
// ---------------------------------------------------------------------------
__global__ void __launch_bounds__(NT, 8) solve_kernel(
    const float* __restrict__ E, const float* __restrict__ R,
    const float* __restrict__ K, const float* __restrict__ S0,
    const float* __restrict__ SC, float* __restrict__ out)
{
    __shared__ float red[3][4];
    int tid  = threadIdx.x;
    int lane = tid & 31;
    int warp = tid >> 5;
    int b    = blockIdx.x;

    // Phase 0: setup (blocks 0..15 cover all 2048 bins)
    if (b < NE / NT) setup_bin(b * NT + tid, E, R, K, S0, SC);
    grid_barrier();

    // Phases 1-3: upper-half Jacobi (rows 1024..2046), one row per block
    {
        int ru = NE/2 + b;               // 1024..2047
        bool act = (ru <= NE - 2);
        if (act) sweep_row(ru, K, 0, 1, NE, 0, red, tid, lane, warp);
        grid_barrier();
        if (act) sweep_row(ru, K, 1, 0, NE, 0, red, tid, lane, warp);
        grid_barrier();
        if (act) sweep_row(ru, K, 0, 1, NE, 0, red, tid, lane, warp);
        grid_barrier();
    }

    // Phase 4: fold upper half (buffer 1) into lower rows' RHS, one row/block
    accum_row(b, K, 1, red, tid, lane, warp);
    grid_barrier();

    // Phases 5-6: lower-half Jacobi (rows 0..1023, j in (i,1024), RHS = s2)
    sweep_row(b, K, 0, 1, NE/2, 1, red, tid, lane, warp);
    grid_barrier();
    sweep_row(b, K, 1, 0, NE/2, 1, red, tid, lane, warp);
    grid_barrier();

    // Phase 7: write output (lower half from buf 0, upper half from buf 1)
    if (b < NE / NT) {
        int i = b * NT + tid;
        out[i] = E[i];
        int buf = (i < NE/2) ? 0 : 1;
#pragma unroll
        for (int x = 0; x < NX; x++) {
            float f = g_F[buf][x][i];
            out[(x + 1) * NE + i] = (f > 0.0f) ? f : 0.0f;
        }
    }
}

extern "C" void kernel_launch(void* const* d_in, const int* in_sizes, int n_in,
                              void* d_out, int out_size)
{
    const float* E  = (const float*)d_in[0];
    const float* R  = (const float*)d_in[1];
    const float* K  = (const float*)d_in[2];
    const float* S0 = (const float*)d_in[3];
    const float* SC = (const float*)d_in[4];
    float* out = (float*)d_out;

    solve_kernel<<<NB, NT>>>(E, R, K, S0, SC, out);
}

// round 13
// speedup vs baseline: 1.6116x; 1.5781x over previous
#include <cuda_runtime.h>
#include <math.h>

#define NE 2048
#define NX 3
#define NT 128

// Scratch (allocation-free): all __device__ globals.
__device__ float g_s[NX][NE];        // static RHS (SC + last-column terms)
__device__ float g_s2[NX][NE];       // extended RHS for lower rows
__device__ float g_Binv[NX*NX][NE];  // per-bin 3x3 inverse of B_i
__device__ float g_c[NE];            // c_j = dy*E_j
__device__ float g_F[2][NX][NE];     // double-buffered solution
__device__ float g_wF[2][NX][NE];    // double-buffered c_j*F_j (col NE-1 == 0)

__device__ __forceinline__ float4 ld4(const float* __restrict__ p, int j) {
    return *reinterpret_cast<const float4*>(p + j);
}

#define DECLARE_K_STREAMS(K, i)                                                \
    const float* __restrict__ k00 = K + ((size_t)((0*NX+0)*NE + i))*NE;        \
    const float* __restrict__ k01 = K + ((size_t)((0*NX+1)*NE + i))*NE;        \
    const float* __restrict__ k02 = K + ((size_t)((0*NX+2)*NE + i))*NE;        \
    const float* __restrict__ k10 = K + ((size_t)((1*NX+0)*NE + i))*NE;        \
    const float* __restrict__ k11 = K + ((size_t)((1*NX+1)*NE + i))*NE;        \
    const float* __restrict__ k12 = K + ((size_t)((1*NX+2)*NE + i))*NE;        \
    const float* __restrict__ k20 = K + ((size_t)((2*NX+0)*NE + i))*NE;        \
    const float* __restrict__ k21 = K + ((size_t)((2*NX+1)*NE + i))*NE;        \
    const float* __restrict__ k22 = K + ((size_t)((2*NX+2)*NE + i))*NE;

#define ACCUM(JB, W0, W1, W2)                                                  \
    do {                                                                       \
        float4 kk;                                                             \
        kk = ld4(k00, JB); y0 += kk.x*W0.x + kk.y*W0.y + kk.z*W0.z + kk.w*W0.w;\
        kk = ld4(k01, JB); y0 += kk.x*W1.x + kk.y*W1.y + kk.z*W1.z + kk.w*W1.w;\
        kk = ld4(k02, JB); y0 += kk.x*W2.x + kk.y*W2.y + kk.z*W2.z + kk.w*W2.w;\
        kk = ld4(k10, JB); y1 += kk.x*W0.x + kk.y*W0.y + kk.z*W0.z + kk.w*W0.w;\
        kk = ld4(k11, JB); y1 += kk.x*W1.x + kk.y*W1.y + kk.z*W1.z + kk.w*W1.w;\
        kk = ld4(k12, JB); y1 += kk.x*W2.x + kk.y*W2.y + kk.z*W2.z + kk.w*W2.w;\
        kk = ld4(k20, JB); y2 += kk.x*W0.x + kk.y*W0.y + kk.z*W0.z + kk.w*W0.w;\
        kk = ld4(k21, JB); y2 += kk.x*W1.x + kk.y*W1.y + kk.z*W1.z + kk.w*W1.w;\
        kk = ld4(k22, JB); y2 += kk.x*W2.x + kk.y*W2.y + kk.z*W2.z + kk.w*W2.w;\
    } while (0)

// Block-level reduce of (y0,y1,y2); result valid on tid==0.
__device__ __forceinline__ void block_reduce3(
    float& y0, float& y1, float& y2, float red[3][4], int tid, int lane, int warp)
{
#pragma unroll
    for (int o = 16; o > 0; o >>= 1) {
        y0 += __shfl_xor_sync(0xffffffffu, y0, o);
        y1 += __shfl_xor_sync(0xffffffffu, y1, o);
        y2 += __shfl_xor_sync(0xffffffffu, y2, o);
    }
    if (lane == 0) { red[0][warp] = y0; red[1][warp] = y1; red[2][warp] = y2; }
    __syncthreads();
    if (tid == 0) {
        y0 = red[0][0] + red[0][1] + red[0][2] + red[0][3];
        y1 = red[1][0] + red[1][1] + red[1][2] + red[1][3];
        y2 = red[2][0] + red[2][1] + red[2][2] + red[2][3];
    }
}

// ---------------------------------------------------------------------------
// Setup: dy, src_last, F[:,NE-1], c, Binv, s, initial guess F0 = Binv*s (buf0)
// ---------------------------------------------------------------------------
__global__ __launch_bounds__(NT) void setup_kernel(
    const float* __restrict__ E, const float* __restrict__ R,
    const float* __restrict__ K, const float* __restrict__ S0,
    const float* __restrict__ SC)
{
    int i = blockIdx.x * NT + threadIdx.x;
    if (i >= NE) return;

    const float dy = logf(E[NE-1] / E[0]) / (float)(NE - 1);

    float srcl[NX];
#pragma unroll
    for (int p = 0; p < NX; p++) srcl[p] = S0[p] / R[p*NE + NE-1];

    float Flast[NX];
#pragma unroll
    for (int x = 0; x < NX; x++) {
        float acc = SC[x*NE + NE-1];
#pragma unroll
        for (int p = 0; p < NX; p++)
            acc += K[((size_t)((x*NX + p)*NE + (NE-1)))*NE + (NE-1)] * srcl[p];
        Flast[x] = acc / R[x*NE + NE-1];
    }

    if (i == NE-1) {
#pragma unroll
        for (int x = 0; x < NX; x++) {
            g_F[0][x][NE-1] = Flast[x];
            g_F[1][x][NE-1] = Flast[x];
            g_wF[0][x][NE-1] = 0.0f;   // sentinel: j=NE-1 folded into s
            g_wF[1][x][NE-1] = 0.0f;
        }
        return;
    }

    const float ci = dy * E[i];
    g_c[i] = ci;
    const float w_last = 0.5f * dy * E[NE-1];

    float Bm[3][3];
    float sv[NX];
#pragma unroll
    for (int x = 0; x < NX; x++) {
        float acc = SC[x*NE + i];
#pragma unroll
        for (int p = 0; p < NX; p++) {
            size_t rb = ((size_t)((x*NX + p)*NE + i)) * NE;
            float Kii = K[rb + i];
            float Kil = K[rb + NE-1];
            Bm[x][p] = -0.5f * ci * Kii + ((x == p) ? R[x*NE + i] : 0.0f);
            acc += Kil * (w_last * Flast[p] + srcl[p]);
        }
        sv[x] = acc;
    }

    float c00 = Bm[1][1]*Bm[2][2] - Bm[1][2]*Bm[2][1];
    float c01 = Bm[1][2]*Bm[2][0] - Bm[1][0]*Bm[2][2];
    float c02 = Bm[1][0]*Bm[2][1] - Bm[1][1]*Bm[2][0];
    float det = Bm[0][0]*c00 + Bm[0][1]*c01 + Bm[0][2]*c02;
    float id  = 1.0f / det;
    float inv[3][3];
    inv[0][0] = c00 * id;
    inv[0][1] = (Bm[0][2]*Bm[2][1] - Bm[0][1]*Bm[2][2]) * id;
    inv[0][2] = (Bm[0][1]*Bm[1][2] - Bm[0][2]*Bm[1][1]) * id;
    inv[1][0] = c01 * id;
    inv[1][1] = (Bm[0][0]*Bm[2][2] - Bm[0][2]*Bm[2][0]) * id;
    inv[1][2] = (Bm[0][2]*Bm[1][0] - Bm[0][0]*Bm[1][2]) * id;
    inv[2][0] = c02 * id;
    inv[2][1] = (Bm[0][1]*Bm[2][0] - Bm[0][0]*Bm[2][1]) * id;
    inv[2][2] = (Bm[0][0]*Bm[1][1] - Bm[0][1]*Bm[1][0]) * id;

#pragma unroll
    for (int x = 0; x < NX; x++) {
        g_s[x][i] = sv[x];
#pragma unroll
        for (int p = 0; p < NX; p++) g_Binv[x*NX + p][i] = inv[x][p];
    }

#pragma unroll
    for (int x = 0; x < NX; x++) {
        float f = inv[x][0]*sv[0] + inv[x][1]*sv[1] + inv[x][2]*sv[2];
        g_F[0][x][i]  = f;
        g_wF[0][x][i] = ci * f;
    }
}

// ---------------------------------------------------------------------------
// Upper sweep (one row per block): rows 1024..2046, j in (i, 2048), RHS = s.
// ---------------------------------------------------------------------------
__global__ __launch_bounds__(NT) void sweep_up_kernel(
    const float* __restrict__ K, int src, int dst)
{
    __shared__ float red[3][4];
    int tid = threadIdx.x, lane = tid & 31, warp = tid >> 5;
    int i = NE/2 + blockIdx.x;       // 1024..2046 (grid = 1023)

    const float* __restrict__ wf0 = g_wF[src][0];
    const float* __restrict__ wf1 = g_wF[src][1];
    const float* __restrict__ wf2 = g_wF[src][2];
    DECLARE_K_STREAMS(K, i)

    float y0 = 0.f, y1 = 0.f, y2 = 0.f;
    int jv = (i + 1) & ~3;
    int jb = jv + 4 * tid;

    if (jb < NE) {
        float4 w0 = ld4(wf0, jb), w1 = ld4(wf1, jb), w2 = ld4(wf2, jb);
        if (jb + 0 <= i) { w0.x = 0.f; w1.x = 0.f; w2.x = 0.f; }
        if (jb + 1 <= i) { w0.y = 0.f; w1.y = 0.f; w2.y = 0.f; }
        if (jb + 2 <= i) { w0.z = 0.f; w1.z = 0.f; w2.z = 0.f; }
        if (jb + 3 <= i) { w0.w = 0.f; w1.w = 0.f; w2.w = 0.f; }
        ACCUM(jb, w0, w1, w2);
        jb += 4 * NT;
    }
    for (; jb < NE; jb += 4 * NT) {
        float4 w0 = ld4(wf0, jb), w1 = ld4(wf1, jb), w2 = ld4(wf2, jb);
        ACCUM(jb, w0, w1, w2);
    }

    block_reduce3(y0, y1, y2, red, tid, lane, warp);

    if (tid == 0) {
        float s0 = g_s[0][i] + y0;
        float s1 = g_s[1][i] + y1;
        float s2 = g_s[2][i] + y2;
        float f0 = g_Binv[0][i]*s0 + g_Binv[1][i]*s1 + g_Binv[2][i]*s2;
        float f1 = g_Binv[3][i]*s0 + g_Binv[4][i]*s1 + g_Binv[5][i]*s2;
        float f2 = g_Binv[6][i]*s0 + g_Binv[7][i]*s1 + g_Binv[8][i]*s2;
        float ci = g_c[i];
        g_F[dst][0][i]  = f0;  g_wF[dst][0][i] = ci * f0;
        g_F[dst][1][i]  = f1;  g_wF[dst][1][i] = ci * f1;
        g_F[dst][2][i]  = f2;  g_wF[dst][2][i] = ci * f2;
    }
}

// ---------------------------------------------------------------------------
// Accum + upper output + lower guess refresh (one lower row per block):
//   y_i = sum_{p, j in [1024,2048)} K[x][p][i][j] * wF[buf0][p][j]  (upper final)
//   s2  = s + y  (stored)
//   F0' = Binv * s2 -> buf0 lower (refreshed guess for the single lower sweep)
//   out rows for upper row u = 1024 + i  (from buf0, incl. u = 2047)
// ---------------------------------------------------------------------------
__global__ __launch_bounds__(NT) void accum_kernel(
    const float* __restrict__ K, const float* __restrict__ E,
    float* __restrict__ out)
{
    __shared__ float red[3][4];
    int tid = threadIdx.x, lane = tid & 31, warp = tid >> 5;
    int i = blockIdx.x;              // 0..1023

    const float* __restrict__ wf0 = g_wF[0][0];
    const float* __restrict__ wf1 = g_wF[0][1];
    const float* __restrict__ wf2 = g_wF[0][2];
    DECLARE_K_STREAMS(K, i)

    float y0 = 0.f, y1 = 0.f, y2 = 0.f;
#pragma unroll 1
    for (int pass = 0; pass < 2; pass++) {
        int jb = NE/2 + pass * (4 * NT) + 4 * tid;
        float4 w0 = ld4(wf0, jb), w1 = ld4(wf1, jb), w2 = ld4(wf2, jb);
        ACCUM(jb, w0, w1, w2);
    }

    block_reduce3(y0, y1, y2, red, tid, lane, warp);

    if (tid == 0) {
        float s0 = g_s[0][i] + y0;
        float s1 = g_s[1][i] + y1;
        float s2 = g_s[2][i] + y2;
        g_s2[0][i] = s0; g_s2[1][i] = s1; g_s2[2][i] = s2;
        float f0 = g_Binv[0][i]*s0 + g_Binv[1][i]*s1 + g_Binv[2][i]*s2;
        float f1 = g_Binv[3][i]*s0 + g_Binv[4][i]*s1 + g_Binv[5][i]*s2;
        float f2 = g_Binv[6][i]*s0 + g_Binv[7][i]*s1 + g_Binv[8][i]*s2;
        float ci = g_c[i];
        g_F[0][0][i] = f0;  g_wF[0][0][i] = ci * f0;   // refreshed lower guess
        g_F[0][1][i] = f1;  g_wF[0][1][i] = ci * f1;
        g_F[0][2][i] = f2;  g_wF[0][2][i] = ci * f2;

        // upper-half output: row u = 1024 + i (upper final lives in buf0)
        int u = NE/2 + i;
        out[u] = E[u];
#pragma unroll
        for (int x = 0; x < NX; x++) {
            float f = g_F[0][x][u];
            out[(x + 1) * NE + u] = (f > 0.0f) ? f : 0.0f;
        }
    }
}

// ---------------------------------------------------------------------------
// Single lower sweep + lower output (one row per block):
//   y = sum_{p, j in (i, 1024)} K[x][p][i][j] * wF[buf0][p][j]  (refreshed guess)
//   F = Binv * (s2 + y); write out directly (no buffer store).
// ---------------------------------------------------------------------------
__global__ __launch_bounds__(NT) void low_out_kernel(
    const float* __restrict__ K, const float* __restrict__ E,
    float* __restrict__ out)
{
    __shared__ float red[3][4];
    int tid = threadIdx.x, lane = tid & 31, warp = tid >> 5;
    int i = blockIdx.x;              // 0..1023

    const float* __restrict__ wf0 = g_wF[0][0];
    const float* __restrict__ wf1 = g_wF[0][1];
    const float* __restrict__ wf2 = g_wF[0][2];
    DECLARE_K_STREAMS(K, i)

    float y0 = 0.f, y1 = 0.f, y2 = 0.f;
    int jv = (i + 1) & ~3;
    int jb = jv + 4 * tid;

    if (jb < NE/2) {
        float4 w0 = ld4(wf0, jb), w1 = ld4(wf1, jb), w2 = ld4(wf2, jb);
        if (jb + 0 <= i) { w0.x = 0.f; w1.x = 0.f; w2.x = 0.f; }
        if (jb + 1 <= i) { w0.y = 0.f; w1.y = 0.f; w2.y = 0.f; }
        if (jb + 2 <= i) { w0.z = 0.f; w1.z = 0.f; w2.z = 0.f; }
        if (jb + 3 <= i) { w0.w = 0.f; w1.w = 0.f; w2.w = 0.f; }
        ACCUM(jb, w0, w1, w2);
        jb += 4 * NT;
    }
    for (; jb < NE/2; jb += 4 * NT) {
        float4 w0 = ld4(wf0, jb), w1 = ld4(wf1, jb), w2 = ld4(wf2, jb);
        ACCUM(jb, w0, w1, w2);
    }

    block_reduce3(y0, y1, y2, red, tid, lane, warp);

    if (tid == 0) {
        float s0 = g_s2[0][i] + y0;
        float s1 = g_s2[1][i] + y1;
        float s2 = g_s2[2][i] + y2;
        float f0 = g_Binv[0][i]*s0 + g_Binv[1][i]*s1 + g_Binv[2][i]*s2;
        float f1 = g_Binv[3][i]*s0 + g_Binv[4][i]*s1 + g_Binv[5][i]*s2;
        float f2 = g_Binv[6][i]*s0 + g_Binv[7][i]*s1 + g_Binv[8][i]*s2;
        out[i] = E[i];
        out[1*NE + i] = (f0 > 0.0f) ? f0 : 0.0f;
        out[2*NE + i] = (f1 > 0.0f) ? f1 : 0.0f;
        out[3*NE + i] = (f2 > 0.0f) ? f2 : 0.0f;
    }
}

extern "C" void kernel_launch(void* const* d_in, const int* in_sizes, int n_in,
                              void* d_out, int out_size)
{
    const float* E  = (const float*)d_in[0];
    const float* R  = (const float*)d_in[1];
    const float* K  = (const float*)d_in[2];
    const float* S0 = (const float*)d_in[3];
    const float* SC = (const float*)d_in[4];
    float* out = (float*)d_out;

    // 1. Setup: B inverses, RHS s, initial guess (buf0, both halves)
    setup_kernel<<<NE/NT, NT>>>(E, R, K, S0, SC);

    // 2-3. Two upper Jacobi sweeps (rows 1024..2046): buf0 -> buf1 -> buf0.
    sweep_up_kernel<<<NE/2 - 1, NT>>>(K, 0, 1);
    sweep_up_kernel<<<NE/2 - 1, NT>>>(K, 1, 0);

    // 4. Fold upper final into lower RHS, refresh lower guess, write upper out.
    accum_kernel<<<NE/2, NT>>>(K, E, out);

    // 5. One lower sweep from refreshed guess; writes lower out directly.
    low_out_kernel<<<NE/2, NT>>>(K, E, out);
}

// round 14
// speedup vs baseline: 1.8442x; 1.1443x over previous
#include <cuda_runtime.h>
#include <math.h>

#define NE 2048
#define NX 3
#define NT 128

// Scratch (allocation-free): all __device__ globals.
__device__ float g_s[NX][NE];        // static RHS (SC + last-column terms)
__device__ float g_s2[NX][NE];       // extended RHS for lower rows
__device__ float g_Binv[NX*NX][NE];  // per-bin 3x3 inverse of B_i
__device__ float g_c[NE];            // c_j = dy*E_j
__device__ float g_F[2][NX][NE];     // double-buffered solution
__device__ float g_wF[2][NX][NE];    // double-buffered c_j*F_j (col NE-1 == 0)

__device__ __forceinline__ float4 ld4(const float* __restrict__ p, int j) {
    return *reinterpret_cast<const float4*>(p + j);
}

#define DECLARE_K_STREAMS(K, i)                                                \
    const float* __restrict__ k00 = K + ((size_t)((0*NX+0)*NE + i))*NE;        \
    const float* __restrict__ k01 = K + ((size_t)((0*NX+1)*NE + i))*NE;        \
    const float* __restrict__ k02 = K + ((size_t)((0*NX+2)*NE + i))*NE;        \
    const float* __restrict__ k10 = K + ((size_t)((1*NX+0)*NE + i))*NE;        \
    const float* __restrict__ k11 = K + ((size_t)((1*NX+1)*NE + i))*NE;        \
    const float* __restrict__ k12 = K + ((size_t)((1*NX+2)*NE + i))*NE;        \
    const float* __restrict__ k20 = K + ((size_t)((2*NX+0)*NE + i))*NE;        \
    const float* __restrict__ k21 = K + ((size_t)((2*NX+1)*NE + i))*NE;        \
    const float* __restrict__ k22 = K + ((size_t)((2*NX+2)*NE + i))*NE;

#define ACCUM(JB, W0, W1, W2)                                                  \
    do {                                                                       \
        float4 kk;                                                             \
        kk = ld4(k00, JB); y0 += kk.x*W0.x + kk.y*W0.y + kk.z*W0.z + kk.w*W0.w;\
        kk = ld4(k01, JB); y0 += kk.x*W1.x + kk.y*W1.y + kk.z*W1.z + kk.w*W1.w;\
        kk = ld4(k02, JB); y0 += kk.x*W2.x + kk.y*W2.y + kk.z*W2.z + kk.w*W2.w;\
        kk = ld4(k10, JB); y1 += kk.x*W0.x + kk.y*W0.y + kk.z*W0.z + kk.w*W0.w;\
        kk = ld4(k11, JB); y1 += kk.x*W1.x + kk.y*W1.y + kk.z*W1.z + kk.w*W1.w;\
        kk = ld4(k12, JB); y1 += kk.x*W2.x + kk.y*W2.y + kk.z*W2.z + kk.w*W2.w;\
        kk = ld4(k20, JB); y2 += kk.x*W0.x + kk.y*W0.y + kk.z*W0.z + kk.w*W0.w;\
        kk = ld4(k21, JB); y2 += kk.x*W1.x + kk.y*W1.y + kk.z*W1.z + kk.w*W1.w;\
        kk = ld4(k22, JB); y2 += kk.x*W2.x + kk.y*W2.y + kk.z*W2.z + kk.w*W2.w;\
    } while (0)

// Block-level reduce of (y0,y1,y2); result valid on tid==0.
__device__ __forceinline__ void block_reduce3(
    float& y0, float& y1, float& y2, float red[3][4], int tid, int lane, int warp)
{
#pragma unroll
    for (int o = 16; o > 0; o >>= 1) {
        y0 += __shfl_xor_sync(0xffffffffu, y0, o);
        y1 += __shfl_xor_sync(0xffffffffu, y1, o);
        y2 += __shfl_xor_sync(0xffffffffu, y2, o);
    }
    if (lane == 0) { red[0][warp] = y0; red[1][warp] = y1; red[2][warp] = y2; }
    __syncthreads();
    if (tid == 0) {
        y0 = red[0][0] + red[0][1] + red[0][2] + red[0][3];
        y1 = red[1][0] + red[1][1] + red[1][2] + red[1][3];
        y2 = red[2][0] + red[2][1] + red[2][2] + red[2][3];
    }
}

// ---------------------------------------------------------------------------
// Setup: dy, src_last, F[:,NE-1], c, Binv, s, initial guess F0 = Binv*s (buf0)
// ---------------------------------------------------------------------------
__global__ __launch_bounds__(NT) void setup_kernel(
    const float* __restrict__ E, const float* __restrict__ R,
    const float* __restrict__ K, const float* __restrict__ S0,
    const float* __restrict__ SC)
{
    int i = blockIdx.x * NT + threadIdx.x;
    if (i >= NE) return;

    const float dy = logf(E[NE-1] / E[0]) / (float)(NE - 1);

    float srcl[NX];
#pragma unroll
    for (int p = 0; p < NX; p++) srcl[p] = S0[p] / R[p*NE + NE-1];

    float Flast[NX];
#pragma unroll
    for (int x = 0; x < NX; x++) {
        float acc = SC[x*NE + NE-1];
#pragma unroll
        for (int p = 0; p < NX; p++)
            acc += K[((size_t)((x*NX + p)*NE + (NE-1)))*NE + (NE-1)] * srcl[p];
        Flast[x] = acc / R[x*NE + NE-1];
    }

    if (i == NE-1) {
#pragma unroll
        for (int x = 0; x < NX; x++) {
            g_F[0][x][NE-1] = Flast[x];
            g_F[1][x][NE-1] = Flast[x];
            g_wF[0][x][NE-1] = 0.0f;   // sentinel: j=NE-1 folded into s
            g_wF[1][x][NE-1] = 0.0f;
        }
        return;
    }

    const float ci = dy * E[i];
    g_c[i] = ci;
    const float w_last = 0.5f * dy * E[NE-1];

    float Bm[3][3];
    float sv[NX];
#pragma unroll
    for (int x = 0; x < NX; x++) {
        float acc = SC[x*NE + i];
#pragma unroll
        for (int p = 0; p < NX; p++) {
            size_t rb = ((size_t)((x*NX + p)*NE + i)) * NE;
            float Kii = K[rb + i];
            float Kil = K[rb + NE-1];
            Bm[x][p] = -0.5f * ci * Kii + ((x == p) ? R[x*NE + i] : 0.0f);
            acc += Kil * (w_last * Flast[p] + srcl[p]);
        }
        sv[x] = acc;
    }

    float c00 = Bm[1][1]*Bm[2][2] - Bm[1][2]*Bm[2][1];
    float c01 = Bm[1][2]*Bm[2][0] - Bm[1][0]*Bm[2][2];
    float c02 = Bm[1][0]*Bm[2][1] - Bm[1][1]*Bm[2][0];
    float det = Bm[0][0]*c00 + Bm[0][1]*c01 + Bm[0][2]*c02;
    float id  = 1.0f / det;
    float inv[3][3];
    inv[0][0] = c00 * id;
    inv[0][1] = (Bm[0][2]*Bm[2][1] - Bm[0][1]*Bm[2][2]) * id;
    inv[0][2] = (Bm[0][1]*Bm[1][2] - Bm[0][2]*Bm[1][1]) * id;
    inv[1][0] = c01 * id;
    inv[1][1] = (Bm[0][0]*Bm[2][2] - Bm[0][2]*Bm[2][0]) * id;
    inv[1][2] = (Bm[0][2]*Bm[1][0] - Bm[0][0]*Bm[1][2]) * id;
    inv[2][0] = c02 * id;
    inv[2][1] = (Bm[0][1]*Bm[2][0] - Bm[0][0]*Bm[2][1]) * id;
    inv[2][2] = (Bm[0][0]*Bm[1][1] - Bm[0][1]*Bm[1][0]) * id;

#pragma unroll
    for (int x = 0; x < NX; x++) {
        g_s[x][i] = sv[x];
#pragma unroll
        for (int p = 0; p < NX; p++) g_Binv[x*NX + p][i] = inv[x][p];
    }

#pragma unroll
    for (int x = 0; x < NX; x++) {
        float f = inv[x][0]*sv[0] + inv[x][1]*sv[1] + inv[x][2]*sv[2];
        g_F[0][x][i]  = f;
        g_wF[0][x][i] = ci * f;
    }
}

// ---------------------------------------------------------------------------
// Single upper sweep (one row per block): rows 1024..2046, j in (i, 2048).
// Reads guess buf0, writes buf1.
// ---------------------------------------------------------------------------
__global__ __launch_bounds__(NT) void sweep_up_kernel(const float* __restrict__ K)
{
    __shared__ float red[3][4];
    int tid = threadIdx.x, lane = tid & 31, warp = tid >> 5;
    int i = NE/2 + blockIdx.x;       // 1024..2046 (grid = 1023)

    const float* __restrict__ wf0 = g_wF[0][0];
    const float* __restrict__ wf1 = g_wF[0][1];
    const float* __restrict__ wf2 = g_wF[0][2];
    DECLARE_K_STREAMS(K, i)

    float y0 = 0.f, y1 = 0.f, y2 = 0.f;
    int jv = (i + 1) & ~3;
    int jb = jv + 4 * tid;

    if (jb < NE) {
        float4 w0 = ld4(wf0, jb), w1 = ld4(wf1, jb), w2 = ld4(wf2, jb);
        if (jb + 0 <= i) { w0.x = 0.f; w1.x = 0.f; w2.x = 0.f; }
        if (jb + 1 <= i) { w0.y = 0.f; w1.y = 0.f; w2.y = 0.f; }
        if (jb + 2 <= i) { w0.z = 0.f; w1.z = 0.f; w2.z = 0.f; }
        if (jb + 3 <= i) { w0.w = 0.f; w1.w = 0.f; w2.w = 0.f; }
        ACCUM(jb, w0, w1, w2);
        jb += 4 * NT;
    }
    for (; jb < NE; jb += 4 * NT) {
        float4 w0 = ld4(wf0, jb), w1 = ld4(wf1, jb), w2 = ld4(wf2, jb);
        ACCUM(jb, w0, w1, w2);
    }

    block_reduce3(y0, y1, y2, red, tid, lane, warp);

    if (tid == 0) {
        float s0 = g_s[0][i] + y0;
        float s1 = g_s[1][i] + y1;
        float s2 = g_s[2][i] + y2;
        float f0 = g_Binv[0][i]*s0 + g_Binv[1][i]*s1 + g_Binv[2][i]*s2;
        float f1 = g_Binv[3][i]*s0 + g_Binv[4][i]*s1 + g_Binv[5][i]*s2;
        float f2 = g_Binv[6][i]*s0 + g_Binv[7][i]*s1 + g_Binv[8][i]*s2;
        float ci = g_c[i];
        g_F[1][0][i]  = f0;  g_wF[1][0][i] = ci * f0;
        g_F[1][1][i]  = f1;  g_wF[1][1][i] = ci * f1;
        g_F[1][2][i]  = f2;  g_wF[1][2][i] = ci * f2;
    }
}

// ---------------------------------------------------------------------------
// Accum + upper output + lower guess refresh (one lower row per block):
//   y_i = sum_{p, j in [1024,2048)} K[x][p][i][j] * wF[buf1][p][j]  (upper final)
//   s2  = s + y  (stored)
//   F0' = Binv * s2 -> buf0 lower (refreshed guess for the single lower sweep)
//   out rows for upper row u = 1024 + i  (from buf1, incl. u = 2047)
// ---------------------------------------------------------------------------
__global__ __launch_bounds__(NT) void accum_kernel(
    const float* __restrict__ K, const float* __restrict__ E,
    float* __restrict__ out)
{
    __shared__ float red[3][4];
    int tid = threadIdx.x, lane = tid & 31, warp = tid >> 5;
    int i = blockIdx.x;              // 0..1023

    const float* __restrict__ wf0 = g_wF[1][0];
    const float* __restrict__ wf1 = g_wF[1][1];
    const float* __restrict__ wf2 = g_wF[1][2];
    DECLARE_K_STREAMS(K, i)

    float y0 = 0.f, y1 = 0.f, y2 = 0.f;
#pragma unroll 1
    for (int pass = 0; pass < 2; pass++) {
        int jb = NE/2 + pass * (4 * NT) + 4 * tid;
        float4 w0 = ld4(wf0, jb), w1 = ld4(wf1, jb), w2 = ld4(wf2, jb);
        ACCUM(jb, w0, w1, w2);
    }

    block_reduce3(y0, y1, y2, red, tid, lane, warp);

    if (tid == 0) {
        float s0 = g_s[0][i] + y0;
        float s1 = g_s[1][i] + y1;
        float s2 = g_s[2][i] + y2;
        g_s2[0][i] = s0; g_s2[1][i] = s1; g_s2[2][i] = s2;
        float f0 = g_Binv[0][i]*s0 + g_Binv[1][i]*s1 + g_Binv[2][i]*s2;
        float f1 = g_Binv[3][i]*s0 + g_Binv[4][i]*s1 + g_Binv[5][i]*s2;
        float f2 = g_Binv[6][i]*s0 + g_Binv[7][i]*s1 + g_Binv[8][i]*s2;
        float ci = g_c[i];
        g_F[0][0][i] = f0;  g_wF[0][0][i] = ci * f0;   // refreshed lower guess
        g_F[0][1][i] = f1;  g_wF[0][1][i] = ci * f1;
        g_F[0][2][i] = f2;  g_wF[0][2][i] = ci * f2;

        // upper-half output: row u = 1024 + i (upper final lives in buf1)
        int u = NE/2 + i;
        out[u] = E[u];
#pragma unroll
        for (int x = 0; x < NX; x++) {
            float f = g_F[1][x][u];
            out[(x + 1) * NE + u] = (f > 0.0f) ? f : 0.0f;
        }
    }
}

// ---------------------------------------------------------------------------
// Single lower sweep + lower output (one row per block):
//   y = sum_{p, j in (i, 1024)} K[x][p][i][j] * wF[buf0][p][j]  (refreshed guess)
//   F = Binv * (s2 + y); write out directly (no buffer store).
// ---------------------------------------------------------------------------
__global__ __launch_bounds__(NT) void low_out_kernel(
    const float* __restrict__ K, const float* __restrict__ E,
    float* __restrict__ out)
{
    __shared__ float red[3][4];
    int tid = threadIdx.x, lane = tid & 31, warp = tid >> 5;
    int i = blockIdx.x;              // 0..1023

    const float* __restrict__ wf0 = g_wF[0][0];
    const float* __restrict__ wf1 = g_wF[0][1];
    const float* __restrict__ wf2 = g_wF[0][2];
    DECLARE_K_STREAMS(K, i)

    float y0 = 0.f, y1 = 0.f, y2 = 0.f;
    int jv = (i + 1) & ~3;
    int jb = jv + 4 * tid;

    if (jb < NE/2) {
        float4 w0 = ld4(wf0, jb), w1 = ld4(wf1, jb), w2 = ld4(wf2, jb);
        if (jb + 0 <= i) { w0.x = 0.f; w1.x = 0.f; w2.x = 0.f; }
        if (jb + 1 <= i) { w0.y = 0.f; w1.y = 0.f; w2.y = 0.f; }
        if (jb + 2 <= i) { w0.z = 0.f; w1.z = 0.f; w2.z = 0.f; }
        if (jb + 3 <= i) { w0.w = 0.f; w1.w = 0.f; w2.w = 0.f; }
        ACCUM(jb, w0, w1, w2);
        jb += 4 * NT;
    }
    for (; jb < NE/2; jb += 4 * NT) {
        float4 w0 = ld4(wf0, jb), w1 = ld4(wf1, jb), w2 = ld4(wf2, jb);
        ACCUM(jb, w0, w1, w2);
    }

    block_reduce3(y0, y1, y2, red, tid, lane, warp);

    if (tid == 0) {
        float s0 = g_s2[0][i] + y0;
        float s1 = g_s2[1][i] + y1;
        float s2 = g_s2[2][i] + y2;
        float f0 = g_Binv[0][i]*s0 + g_Binv[1][i]*s1 + g_Binv[2][i]*s2;
        float f1 = g_Binv[3][i]*s0 + g_Binv[4][i]*s1 + g_Binv[5][i]*s2;
        float f2 = g_Binv[6][i]*s0 + g_Binv[7][i]*s1 + g_Binv[8][i]*s2;
        out[i] = E[i];
        out[1*NE + i] = (f0 > 0.0f) ? f0 : 0.0f;
        out[2*NE + i] = (f1 > 0.0f) ? f1 : 0.0f;
        out[3*NE + i] = (f2 > 0.0f) ? f2 : 0.0f;
    }
}

extern "C" void kernel_launch(void* const* d_in, const int* in_sizes, int n_in,
                              void* d_out, int out_size)
{
    const float* E  = (const float*)d_in[0];
    const float* R  = (const float*)d_in[1];
    const float* K  = (const float*)d_in[2];
    const float* S0 = (const float*)d_in[3];
    const float* SC = (const float*)d_in[4];
    float* out = (float*)d_out;

    // 1. Setup: B inverses, RHS s, initial guess (buf0, both halves)
    setup_kernel<<<NE/NT, NT>>>(E, R, K, S0, SC);

    // 2. One upper Jacobi sweep (rows 1024..2046): buf0 -> buf1.
    sweep_up_kernel<<<NE/2 - 1, NT>>>(K);

    // 3. Fold upper final into lower RHS, refresh lower guess, write upper out.
    accum_kernel<<<NE/2, NT>>>(K, E, out);

    // 4. One lower sweep from refreshed guess; writes lower out directly.
    low_out_kernel<<<NE/2, NT>>>(K, E, out);
}